// round 17
// baseline (speedup 1.0000x reference)
#include <cuda_runtime.h>
#include <cuda_fp16.h>
#include <cuda_bf16.h>
#include <cstdint>

#define NB 4
#define CC 24
#define EE 16
#define PP (768*768)
#define SLICES 1152          /* blocks per sample, both passes */
#define SPXB (PP/SLICES)     /* 512 px per block */
#define TILES (SPXB/256)     /* 2 tiles of 256 px */
#define AROW 264             /* one-hot row stride in shorts (528 B) */
#define XROW 24              /* x-tile row stride in shorts (48 B) */
#define TRIPB 25
#define VT_TOTAL ((SLICES + TRIPB) * NB)   /* blocks across all var launches */

__device__ float g_sums[NB*CC*EE];
__device__ float g_cnt[NB*CC];
__device__ float g_var[NB*CC];
__device__ float g_tsum[NB];
__device__ float g_tcnt[NB];
__device__ unsigned g_ticket;

// pack two f32 into f16x2: low half = a, high half = b
__device__ __forceinline__ unsigned pack_f16x2(float a, float b) {
    unsigned r;
    asm("cvt.rn.f16x2.f32 %0, %1, %2;" : "=r"(r) : "f"(b), "f"(a));
    return r;
}

// ---------------------------------------------------------------------------
// K1: segment sums via tensor cores, one sample per launch.
// ---------------------------------------------------------------------------
__global__ __launch_bounds__(256) void k_sums(const float* __restrict__ x,
                                              const int* __restrict__ tgt,
                                              int n) {
    __shared__ __align__(16) unsigned short Atile[32*AROW];
    __shared__ __align__(16) unsigned short Xtile[256*XROW];
    __shared__ float bins[32][16];
    __shared__ int   cnts[8][CC];
    const int tid  = threadIdx.x;
    const int wid  = tid >> 5;
    const int lane = tid & 31;

    for (int i = tid; i < 32*AROW; i += 256) Atile[i] = 0;
    for (int i = tid; i < 512;     i += 256) (&bins[0][0])[i] = 0.f;
    for (int i = tid; i < 8*CC;    i += 256) (&cnts[0][0])[i] = 0;
    __syncthreads();

    const float* xn = x   + (size_t)n * EE * PP;
    const int*   tn = tgt + (size_t)n * PP;

    const int q  = wid >> 1;
    const int kh = wid & 1;
    const int Mt = q >> 1, Nt = q & 1;
    const unsigned smemA = (unsigned)__cvta_generic_to_shared(Atile);
    const unsigned smemX = (unsigned)__cvta_generic_to_shared(Xtile);

    float d0 = 0.f, d1 = 0.f, d2 = 0.f, d3 = 0.f;
    int prev_seg = -1;
    const int pxbase = blockIdx.x * SPXB;

    for (int t = 0; t < TILES; ++t) {
        const int p = pxbase + t*256 + tid;
        const int seg = tn[p];

        atomicAdd(&cnts[wid][seg], 1);

        if (prev_seg >= 0) Atile[prev_seg*AROW + tid] = 0;
        Atile[seg*AROW + tid] = 0x3C00;   // f16 1.0
        prev_seg = seg;

        float v[EE];
#pragma unroll
        for (int e = 0; e < EE; ++e) v[e] = xn[e*PP + p];
        unsigned pk[8];
#pragma unroll
        for (int j = 0; j < 8; ++j)
            pk[j] = pack_f16x2(v[2*j], v[2*j+1]);
        uint4* xr = reinterpret_cast<uint4*>(&Xtile[tid*XROW]);
        xr[0] = make_uint4(pk[0], pk[1], pk[2], pk[3]);
        xr[1] = make_uint4(pk[4], pk[5], pk[6], pk[7]);
        __syncthreads();

#pragma unroll
        for (int j = 0; j < 8; ++j) {
            const int Ks = kh*8 + j;
            unsigned a0, a1, a2, a3, b0, b1;
            const unsigned aaddr = smemA
                + (unsigned)(((Mt*16 + (lane & 15))*AROW + Ks*16)*2 + (lane >> 4)*16);
            asm volatile("ldmatrix.sync.aligned.m8n8.x4.shared.b16 "
                         "{%0,%1,%2,%3},[%4];"
                         : "=r"(a0), "=r"(a1), "=r"(a2), "=r"(a3) : "r"(aaddr));
            const unsigned baddr = smemX
                + (unsigned)(((Ks*16 + (lane & 15))*XROW)*2 + Nt*16);
            asm volatile("ldmatrix.sync.aligned.m8n8.x2.trans.shared.b16 "
                         "{%0,%1},[%2];"
                         : "=r"(b0), "=r"(b1) : "r"(baddr));
            asm volatile("mma.sync.aligned.m16n8k16.row.col.f32.f16.f16.f32 "
                         "{%0,%1,%2,%3},{%4,%5,%6,%7},{%8,%9},{%0,%1,%2,%3};"
                         : "+f"(d0), "+f"(d1), "+f"(d2), "+f"(d3)
                         : "r"(a0), "r"(a1), "r"(a2), "r"(a3), "r"(b0), "r"(b1));
        }
        __syncthreads();
    }

    {
        const int r0 = Mt*16 + (lane >> 2);
        const int c0 = Nt*8 + (lane & 3)*2;
        atomicAdd(&bins[r0][c0],     d0);
        atomicAdd(&bins[r0][c0+1],   d1);
        atomicAdd(&bins[r0+8][c0],   d2);
        atomicAdd(&bins[r0+8][c0+1], d3);
    }
    __syncthreads();

    for (int i = tid; i < CC*EE; i += 256)
        atomicAdd(&g_sums[n*CC*EE + i], bins[i >> 4][i & 15]);
    if (tid < CC) {
        int s = 0;
#pragma unroll
        for (int w = 0; w < 8; ++w) s += cnts[w][tid];
        atomicAdd(&g_cnt[n*CC + tid], (float)s);
    }
}

// ---------------------------------------------------------------------------
// K2 (fused, per sample): var slices + triplet row-blocks; launched right
// after sums(n) so sample n's x is still hot in L2. Last block of the LAST
// sample's launch finalizes and re-zeros all state.
// ---------------------------------------------------------------------------
__device__ __forceinline__ void var_block(const float* __restrict__ x,
                                          const int* __restrict__ tgt,
                                          int n, int bx) {
    __shared__ float ms[CC][17];
    __shared__ float vb[8][CC];
    const int tid  = threadIdx.x;
    const int wid  = tid >> 5;

    for (int i = tid; i < CC*EE; i += 256)
        ms[i/EE][i%EE] = g_sums[n*CC*EE + i] / g_cnt[n*CC + i/EE];
    for (int i = tid; i < 8*CC; i += 256) (&vb[0][0])[i] = 0.f;
    __syncthreads();

    const float* xn = x   + (size_t)n * EE * PP;
    const int*   tn = tgt + (size_t)n * PP;

    int pbase = bx * SPXB + tid;
    for (int it = 0; it < TILES; ++it, pbase += 256) {
        const int p = pbase;
        const int seg = tn[p];
        float d2 = 0.f;
#pragma unroll
        for (int e = 0; e < EE; ++e) {
            float diff = xn[e*PP + p] - ms[seg][e];
            d2 += diff * diff;
        }
        float h = sqrtf(d2) - 0.5f;
        h = fmaxf(h, 0.f);
        atomicAdd(&vb[wid][seg], h * h);
    }
    __syncthreads();

    for (int i = tid; i < CC; i += 256) {
        float s = 0.f;
#pragma unroll
        for (int w = 0; w < 8; ++w) s += vb[w][i];
        atomicAdd(&g_var[n*CC + i], s);
    }
}

__device__ __forceinline__ void triplet_block(const int* __restrict__ ea,
                                              const int* __restrict__ er,
                                              int n, int rb) {
    __shared__ float cm[CC][EE];
    __shared__ float dr[200];
    __shared__ int r0s[200], r1s[200];
    __shared__ float da8[8];
    __shared__ int a0s[8], a1s[8];
    __shared__ float reds[256];
    __shared__ int   redc[256];
    const int tid = threadIdx.x;

    for (int i = tid; i < CC*EE; i += 256)
        cm[i/EE][i%EE] = g_sums[n*CC*EE + i] / g_cnt[n*CC + i/EE];
    __syncthreads();

    if (tid < 200) {
        int i0 = er[n*400 + tid], i1 = er[n*400 + 200 + tid];
        r0s[tid] = i0; r1s[tid] = i1;
        float s = 0.f;
#pragma unroll
        for (int e = 0; e < EE; ++e) {
            float df = cm[i0][e] - cm[i1][e] + 1e-6f;
            s += df * df;
        }
        dr[tid] = s;
    }
    if (tid < 8) {
        int a = rb*8 + tid;
        int i0 = ea[n*400 + a], i1 = ea[n*400 + 200 + a];
        a0s[tid] = i0; a1s[tid] = i1;
        float s = 0.f;
#pragma unroll
        for (int e = 0; e < EE; ++e) {
            float df = cm[i0][e] - cm[i1][e] + 1e-6f;
            s += df * df;
        }
        da8[tid] = s;
    }
    __syncthreads();

    float sum = 0.f; int cnt = 0;
    if (tid < 200) {
        const int rr0 = r0s[tid], rr1 = r1s[tid];
        const float drv = dr[tid];
#pragma unroll
        for (int a = 0; a < 8; ++a) {
            const int m = (a0s[a] == rr0) + (a0s[a] == rr1) +
                          (a1s[a] == rr0) + (a1s[a] == rr1);
            if (m == 1) {
                float t = 0.5f * (da8[a] - drv) + 0.01f;
                if (t > 0.f) { sum += t; cnt++; }
            }
        }
    }
    reds[tid] = sum; redc[tid] = cnt;
    __syncthreads();
    for (int s = 128; s > 0; s >>= 1) {
        if (tid < s) { reds[tid] += reds[tid + s]; redc[tid] += redc[tid + s]; }
        __syncthreads();
    }
    if (tid == 0) {
        atomicAdd(&g_tsum[n], reds[0]);
        atomicAdd(&g_tcnt[n], (float)redc[0]);
    }
}

__global__ __launch_bounds__(256) void k_var_trip(const float* __restrict__ x,
                                                  const int* __restrict__ tgt,
                                                  const int* __restrict__ ea,
                                                  const int* __restrict__ er,
                                                  float* __restrict__ out,
                                                  int n) {
    if (blockIdx.x < SLICES) var_block(x, tgt, n, blockIdx.x);
    else                     triplet_block(ea, er, n, blockIdx.x - SLICES);

    // ---- last-block (across all 4 var launches) finalize + state reset ----
    __threadfence();
    __shared__ unsigned isLast;
    const int tid = threadIdx.x;
    if (tid == 0)
        isLast = (atomicAdd(&g_ticket, 1u) == (unsigned)(VT_TOTAL - 1));
    __syncthreads();
    if (!isLast) return;
    __threadfence();   // acquire: see all other blocks' atomics

    __shared__ float red[256];
    float acc = 0.f;
    if (tid < NB*CC) {
        float inv = 1.f / g_cnt[tid];
        float vt = g_var[tid] * inv;
        float s2 = 0.f;
#pragma unroll
        for (int e = 0; e < EE; ++e) {
            float m = g_sums[tid*EE + e] * inv;
            s2 += m * m;
        }
        float rg = sqrtf(s2) - 1.f;
        acc = (vt + rg * rg) * (1.f / (float)CC);
    }
    if (tid < NB) acc += (g_tcnt[tid] > 0.f) ? g_tsum[tid] / g_tcnt[tid] : 0.f;
    red[tid] = acc;
    __syncthreads();
    for (int s = 128; s > 0; s >>= 1) {
        if (tid < s) red[tid] += red[tid + s];
        __syncthreads();
    }
    if (tid == 0) out[0] = red[0] / 16.f;

    // re-zero all accumulator state for the next call (graph replay)
    for (int i = tid; i < NB*CC*EE; i += 256) g_sums[i] = 0.f;
    if (tid < NB*CC) { g_cnt[tid] = 0.f; g_var[tid] = 0.f; }
    if (tid < NB) { g_tsum[tid] = 0.f; g_tcnt[tid] = 0.f; }
    if (tid == 0) g_ticket = 0u;
}

// ---------------------------------------------------------------------------
extern "C" void kernel_launch(void* const* d_in, const int* in_sizes, int n_in,
                              void* d_out, int out_size) {
    const float* x   = (const float*)d_in[0];
    const int*   tgt = (const int*)d_in[1];
    const int*   ea  = (const int*)d_in[2];
    const int*   er  = (const int*)d_in[3];
    float* out = (float*)d_out;

    for (int n = 0; n < NB; ++n) {
        k_sums<<<SLICES, 256>>>(x, tgt, n);
        k_var_trip<<<SLICES + TRIPB, 256>>>(x, tgt, ea, er, out, n);
    }
}